// round 3
// baseline (speedup 1.0000x reference)
#include <cuda_runtime.h>
#include <cuda_bf16.h>
#include <cstdint>

// HarmonicLowering: x (8,32,256,512) f32 -> out (8,128,256,512) f32
//   out[b, k*32+c, i, t] = w*x[b,c,idx,t] + (1-w)*x[b,c,idx1,t]
//   prod=i*(k+1), idx=prod>>2, rem=prod&3, w=1-rem/4, idx1=min(idx+1,255)
//
// Pure HBM-streaming kernel: float4 along t, grid ordered so that all rows
// consuming one (b,c) input plane (512 KiB) are contiguous -> L2-resident.
// Streaming stores (__stcs) keep output from evicting the input working set.

static constexpr int BATCH = 8;
static constexpr int C     = 32;
static constexpr int FREQ  = 256;
static constexpr int TIME  = 512;
static constexpr int T4    = TIME / 4;          // 128 float4 per row
static constexpr int K     = 4;                 // F_KERNEL_SIZE

static constexpr int THREADS = 256;
// total float4 outputs = 8*128*256*128 = 33,554,432 -> 131072 blocks of 256
static constexpr long long TOTAL4 = (long long)BATCH * (K * C) * FREQ * T4;
static constexpr int NBLOCKS = (int)(TOTAL4 / THREADS);

__global__ __launch_bounds__(THREADS) void harmonic_lowering_kernel(
    const float4* __restrict__ in, float4* __restrict__ out)
{
    int gid = blockIdx.x * THREADS + threadIdx.x;

    // gid = (((bc)*K + k)*FREQ + i)*T4 + t4   (bc = b*C + c)
    int t4 = gid & (T4 - 1);
    int r  = gid >> 7;           // /T4
    int i  = r & (FREQ - 1);
    r >>= 8;
    int k  = r & (K - 1);
    r >>= 2;                     // r = b*C + c, in [0, 256)

    int prod = i * (k + 1);
    int idx  = prod >> 2;
    int rem  = prod & 3;
    float w  = 1.0f - 0.25f * (float)rem;

    // input plane base: bc * FREQ * T4 = r * 32768
    const float4* base = in + ((unsigned)r << 15);

    float4 g0 = __ldg(base + (idx << 7) + t4);
    float4 o;
    if (rem) {                   // warp-uniform: i,k constant across t4 group
        int idx1 = idx + 1;
        if (idx1 > FREQ - 1) idx1 = FREQ - 1;
        float4 g1 = __ldg(base + (idx1 << 7) + t4);
        float w1 = 1.0f - w;
        o.x = w * g0.x + w1 * g1.x;
        o.y = w * g0.y + w1 * g1.y;
        o.z = w * g0.z + w1 * g1.z;
        o.w = w * g0.w + w1 * g1.w;
    } else {
        o = g0;                  // w == 1
    }

    // out offset: ((b*(K*C) + k*C + c)*FREQ + i)*T4 + t4
    int b = r >> 5, c = r & (C - 1);
    unsigned off = ((((unsigned)b * (K * C) + (unsigned)k * C + c) << 8) + i) * T4 + t4;
    __stcs(out + off, o);
}

extern "C" void kernel_launch(void* const* d_in, const int* in_sizes, int n_in,
                              void* d_out, int out_size)
{
    const float4* in = (const float4*)d_in[0];
    float4* out = (float4*)d_out;
    harmonic_lowering_kernel<<<NBLOCKS, THREADS>>>(in, out);
}

// round 4
// speedup vs baseline: 1.2429x; 1.2429x over previous
#include <cuda_runtime.h>
#include <cuda_bf16.h>
#include <cstdint>

// HarmonicLowering: x (8,32,256,512) f32 -> out (8,128,256,512) f32
//   out[b, k*32+c, i, t] = w*x[b,c,idx,t] + (1-w)*x[b,c,idx1,t]
//   prod=i*(k+1), idx=prod>>2, rem=prod&3, w=1-rem/4, idx1=min(idx+1,255)
//
// R3: one warp per output row (i,k,bc warp-uniform), each lane processes
// 4 float4 (t4 = lane, +32, +64, +96). Independent loads batched up front
// -> MLP ~4-8 per thread to hide DRAM latency; index math amortized 4x.
// Grid ordered so all rows reading one (b,c) plane (512 KiB) are contiguous
// -> input L2-resident, read ~1x. Streaming stores for write-once output.

static constexpr int BATCH = 8;
static constexpr int C     = 32;
static constexpr int FREQ  = 256;
static constexpr int TIME  = 512;
static constexpr int T4    = TIME / 4;          // 128 float4 per row
static constexpr int K     = 4;

static constexpr int THREADS = 256;             // 8 warps = 8 rows per block
static constexpr int ROWS_TOTAL = BATCH * C * K * FREQ;   // 262144
static constexpr int NBLOCKS = ROWS_TOTAL / 8;            // 32768

__global__ __launch_bounds__(THREADS) void harmonic_lowering_kernel(
    const float4* __restrict__ in, float4* __restrict__ out)
{
    const int lane = threadIdx.x & 31;
    const int wrow = blockIdx.x * 8 + (threadIdx.x >> 5);  // global row id

    // wrow = ((bc)*K + k)*FREQ + i
    int i = wrow & (FREQ - 1);
    int r = wrow >> 8;
    int k = r & (K - 1);
    r >>= 2;                       // bc = b*C + c, in [0,256)

    const int prod = i * (k + 1);
    const int idx  = prod >> 2;
    const int rem  = prod & 3;

    const float4* base = in + ((unsigned)r << 15);      // bc * FREQ * T4
    const float4* p0 = base + (idx << 7) + lane;

    // out offset base: ((b*(K*C) + k*C + c)*FREQ + i)*T4
    const int b = r >> 5, c = r & (C - 1);
    float4* po = out + (((((unsigned)b * (K * C) + (unsigned)k * C + c) << 8) + i) << 7) + lane;

    float4 g0[4];
#pragma unroll
    for (int j = 0; j < 4; j++) g0[j] = __ldg(p0 + j * 32);

    if (rem) {                     // warp-uniform branch
        int idx1 = idx + 1;
        if (idx1 > FREQ - 1) idx1 = FREQ - 1;
        const float4* p1 = base + (idx1 << 7) + lane;
        float4 g1[4];
#pragma unroll
        for (int j = 0; j < 4; j++) g1[j] = __ldg(p1 + j * 32);

        const float w  = 1.0f - 0.25f * (float)rem;
        const float w1 = 1.0f - w;
#pragma unroll
        for (int j = 0; j < 4; j++) {
            float4 o;
            o.x = w * g0[j].x + w1 * g1[j].x;
            o.y = w * g0[j].y + w1 * g1[j].y;
            o.z = w * g0[j].z + w1 * g1[j].z;
            o.w = w * g0[j].w + w1 * g1[j].w;
            __stcs(po + j * 32, o);
        }
    } else {
#pragma unroll
        for (int j = 0; j < 4; j++) __stcs(po + j * 32, g0[j]);
    }
}

extern "C" void kernel_launch(void* const* d_in, const int* in_sizes, int n_in,
                              void* d_out, int out_size)
{
    const float4* in = (const float4*)d_in[0];
    float4* out = (float4*)d_out;
    harmonic_lowering_kernel<<<NBLOCKS, THREADS>>>(in, out);
}